// round 11
// baseline (speedup 1.0000x reference)
#include <cuda_runtime.h>
#include <cuda_fp16.h>
#include <math.h>
#include <stdint.h>

#define VOCABN 128
#define HID    1024
#define BATCHN 256
#define SEQ    256
#define NCTA   128     // recurrence CTAs
#define NFC    20      // fc consumer CTAs
#define GRPSZ  16u

// ---------------- device scratch (no allocations allowed) ----------------
__device__ float    g_P[VOCABN * HID];
__device__ __half   g_hhi [(size_t)SEQ * BATCHN * HID];
__device__ __half   g_hlos[(size_t)SEQ * BATCHN * HID];
__device__ char     g_h8  [(size_t)SEQ * BATCHN * HID];   // rn(h*127)
__device__ char     g_lo8 [(size_t)SEQ * BATCHN * HID];   // rn((h-hi)*2^19) clamped
__device__ __half   g_whhhi[HID * HID];
__device__ char     g_wlo8[HID * HID];                     // rn((W-Whi)*2^21) clamped
__device__ char     g_whi8[HID * HID];                     // rn(Whi*512) clamped
__device__ __half   g_wxhhi[HID * HID], g_wxhlos[HID * HID];
__device__ __half   g_embhi[VOCABN * HID], g_emblos[VOCABN * HID];
__device__ __half   g_fchi[VOCABN * HID],  g_fclos[VOCABN * HID];
__device__ unsigned g_bar[SEQ * 8];                        // per-(step, m-group) counters

// ---------------- PTX helpers ----------------
__device__ __forceinline__ uint32_t smem_u32(const void* p) {
    uint32_t a;
    asm("{ .reg .u64 t; cvta.to.shared.u64 t, %1; cvt.u32.u64 %0, t; }" : "=r"(a) : "l"(p));
    return a;
}
__device__ __forceinline__ uint32_t swz(uint32_t o)   { return o ^ ((o >> 3) & 0x70); }
__device__ __forceinline__ uint32_t swz64(uint32_t o) { return o ^ ((o >> 3) & 0x30); }

#define CP_ASYNC16(dst, src) \
    asm volatile("cp.async.cg.shared.global [%0], [%1], 16;" :: "r"(dst), "l"(src) : "memory")
#define CP_COMMIT() asm volatile("cp.async.commit_group;" ::: "memory")
#define CP_WAIT2()  asm volatile("cp.async.wait_group 2;" ::: "memory")
#define CP_WAIT1()  asm volatile("cp.async.wait_group 1;" ::: "memory")
#define CP_WAIT0()  asm volatile("cp.async.wait_group 0;" ::: "memory")

#define LDSM4(r, addr)                                                            \
    asm volatile("ldmatrix.sync.aligned.m8n8.x4.shared.b16 {%0,%1,%2,%3}, [%4];"  \
        : "=r"((r)[0]), "=r"((r)[1]), "=r"((r)[2]), "=r"((r)[3]) : "r"(addr))
#define LDSM2(r, addr)                                                            \
    asm volatile("ldmatrix.sync.aligned.m8n8.x2.shared.b16 {%0,%1}, [%2];"        \
        : "=r"((r)[0]), "=r"((r)[1]) : "r"(addr))

// fp32-accumulate fp16 mma (main term — exact)
#define MMA16816(c, a, b0, b1)                                                    \
    asm volatile("mma.sync.aligned.m16n8k16.row.col.f32.f16.f16.f32 "             \
        "{%0,%1,%2,%3},{%4,%5,%6,%7},{%8,%9},{%0,%1,%2,%3};"                      \
        : "+f"((c)[0]), "+f"((c)[1]), "+f"((c)[2]), "+f"((c)[3])                   \
        : "r"((a)[0]), "r"((a)[1]), "r"((a)[2]), "r"((a)[3]), "r"(b0), "r"(b1))

// fp16-accumulate mma (fc corrections, from round 10)
#define MMA16816H(c, a, b0, b1)                                                   \
    asm volatile("mma.sync.aligned.m16n8k16.row.col.f16.f16.f16.f16 "             \
        "{%0,%1},{%2,%3,%4,%5},{%6,%7},{%0,%1};"                                  \
        : "+r"((c)[0]), "+r"((c)[1])                                              \
        : "r"((a)[0]), "r"((a)[1]), "r"((a)[2]), "r"((a)[3]), "r"(b0), "r"(b1))

// int8 mma, K=32 (2x MACs per instruction)
#define MMAS8(c, a, b0, b1)                                                       \
    asm volatile("mma.sync.aligned.m16n8k32.row.col.s32.s8.s8.s32 "               \
        "{%0,%1,%2,%3},{%4,%5,%6,%7},{%8,%9},{%0,%1,%2,%3};"                      \
        : "+r"((c)[0]), "+r"((c)[1]), "+r"((c)[2]), "+r"((c)[3])                   \
        : "r"((a)[0]), "r"((a)[1]), "r"((a)[2]), "r"((a)[3]), "r"(b0), "r"(b1))

__device__ __forceinline__ void wait_chunk(int k0) {
    if (k0 < 14)       CP_WAIT2();
    else if (k0 == 14) CP_WAIT1();
    else               CP_WAIT0();
}

// ===========================================================================
// RNN loaders. Stage (16KB): [Ahi fp16 4KB SW128 | h8 2KB SW64 | lo8 2KB SW64
//                             | wlo8 4KB SW64 | whi8 4KB SW64]
// ===========================================================================
__device__ __forceinline__ void rnn_load_W(
    uint32_t STG, int tid, int k0,
    const char* __restrict__ Wlo8, const char* __restrict__ Whi8, int n0)
{
    const uint32_t stg = STG + (uint32_t)(k0 & 3) * 16384;
    const int r = tid >> 2, sg = (tid & 3) * 16;           // 64 rows x 4 segs
    const size_t src = (size_t)(n0 + r) * HID + k0 * 64 + sg;
    const uint32_t off = swz64((uint32_t)(r * 64 + sg));
    CP_ASYNC16(stg + 8192  + off, Wlo8 + src);
    CP_ASYNC16(stg + 12288 + off, Whi8 + src);
    CP_COMMIT();
}

__device__ __forceinline__ void rnn_load_A(
    uint32_t STG, int tid, int k0,
    const __half* __restrict__ Ahi, const char* __restrict__ H8,
    const char* __restrict__ L8, size_t m0)
{
    const uint32_t stg = STG + (uint32_t)(k0 & 3) * 16384;
    {   // Ahi fp16: 32 rows x 8 segs, 1/thread
        const int r = tid >> 3, cc = tid & 7;
        CP_ASYNC16(stg + swz((uint32_t)(r * 128 + cc * 16)),
                   Ahi + (m0 + r) * (size_t)HID + k0 * 64 + cc * 8);
    }
    {   // h8 / lo8: 32 rows x 4 segs each, half the threads each
        const int t = tid & 127, r = t >> 2, sg = (t & 3) * 16;
        const size_t src = (m0 + r) * (size_t)HID + k0 * 64 + sg;
        const uint32_t off = swz64((uint32_t)(r * 64 + sg));
        if (tid < 128) CP_ASYNC16(stg + 4096 + off, H8 + src);
        else           CP_ASYNC16(stg + 6144 + off, L8 + src);
    }
    CP_COMMIT();
}

__device__ __forceinline__ void rnn_load_stage(
    uint32_t STG, int tid, int k0,
    const __half* __restrict__ Ahi, const char* __restrict__ H8,
    const char* __restrict__ L8,
    const char* __restrict__ Wlo8, const char* __restrict__ Whi8,
    size_t m0, int n0)
{
    const uint32_t stg = STG + (uint32_t)(k0 & 3) * 16384;
    {
        const int r = tid >> 3, cc = tid & 7;
        CP_ASYNC16(stg + swz((uint32_t)(r * 128 + cc * 16)),
                   Ahi + (m0 + r) * (size_t)HID + k0 * 64 + cc * 8);
    }
    {
        const int t = tid & 127, r = t >> 2, sg = (t & 3) * 16;
        const size_t src = (m0 + r) * (size_t)HID + k0 * 64 + sg;
        const uint32_t off = swz64((uint32_t)(r * 64 + sg));
        if (tid < 128) CP_ASYNC16(stg + 4096 + off, H8 + src);
        else           CP_ASYNC16(stg + 6144 + off, L8 + src);
    }
    {
        const int r = tid >> 2, sg = (tid & 3) * 16;
        const size_t src = (size_t)(n0 + r) * HID + k0 * 64 + sg;
        const uint32_t off = swz64((uint32_t)(r * 64 + sg));
        CP_ASYNC16(stg + 8192  + off, Wlo8 + src);
        CP_ASYNC16(stg + 12288 + off, Whi8 + src);
    }
    CP_COMMIT();
}

// ---- fc consumer loader (unchanged from round 10) ----
__device__ __forceinline__ void fc_load(
    uint32_t FST, int tid, int slot, int c,
    const __half* __restrict__ Ahi, const __half* __restrict__ Alos,
    const __half* __restrict__ Bhi, const __half* __restrict__ Blos)
{
    const int seg = c >> 4;
    const __half* A = (seg == 2) ? Alos : Ahi;
    const __half* B = (seg == 1) ? Blos : Bhi;
    const uint32_t stg = FST + (uint32_t)slot * 32768;
#pragma unroll
    for (int i = 0; i < 4; i++) {
        int id = tid + i * 256, r = id >> 3;
        uint32_t off = swz((uint32_t)(r * 128 + (id & 7) * 16));
        CP_ASYNC16(stg + off, A + (size_t)r * HID + (c & 15) * 64 + (id & 7) * 8);
    }
#pragma unroll
    for (int i = 0; i < 4; i++) {
        int id = tid + i * 256, r = id >> 3;
        uint32_t off = swz((uint32_t)(r * 128 + (id & 7) * 16));
        CP_ASYNC16(stg + 16384 + off, B + (size_t)r * HID + (c & 15) * 64 + (id & 7) * 8);
    }
    CP_COMMIT();
}

// ===========================================================================
// Fused persistent kernel: CTAs 0..127 recurrence, CTAs 128..147 fc consumers.
// ===========================================================================
__global__ __launch_bounds__(256, 1)
void k_fused(const __half* __restrict__ Whi,
             const char* __restrict__ Wlo8, const char* __restrict__ Whi8,
             const float* __restrict__ bias, const float* __restrict__ P,
             const int* __restrict__ x,
             __half* __restrict__ hhi, __half* __restrict__ hlos,
             char* __restrict__ h8g, char* __restrict__ lo8g,
             const __half* __restrict__ FChi, const __half* __restrict__ FClos,
             const float* __restrict__ fcb, float* __restrict__ outp)
{
    extern __shared__ char smem_raw[];
    const uint32_t sb  = (smem_u32(smem_raw) + 1023u) & ~1023u;
    const int tid = threadIdx.x;
    const int wid = tid >> 5, lane = tid & 31;
    const size_t SLOT = (size_t)BATCHN * HID;

    if (blockIdx.x < NCTA) {
        // =================== RNN path ===================
        const uint32_t PIN = sb;                 // 16 x 8KB pinned Whi (fp16)
        const uint32_t STG = sb + 131072;        // 4 x 16KB stages
        const int wm  = wid >> 2, wn = wid & 3;
        const int g   = lane >> 2, t4 = lane & 3;
        const int grp = blockIdx.x >> 4;
        const size_t m0 = (size_t)grp * 32;
        const int    n0 = (blockIdx.x & 15) * 64;

        {
            const int r = tid >> 3, cc = tid & 7;
#pragma unroll 1
            for (int k0 = 0; k0 < 16; k0++) {
#pragma unroll
                for (int p = 0; p < 2; p++) {
                    int rr = r + p * 32;
                    CP_ASYNC16(PIN + k0 * 8192 + swz((uint32_t)(rr * 128 + cc * 16)),
                               Whi + (size_t)(n0 + rr) * HID + k0 * 64 + cc * 8);
                }
            }
            CP_COMMIT(); CP_WAIT0();
        }
        __syncthreads();

        float2 bb[2];
#pragma unroll
        for (int nf = 0; nf < 2; nf++) {
            int n = n0 + wn * 16 + nf * 8 + t4 * 2;
            bb[nf].x = bias[n]; bb[nf].y = bias[n + 1];
        }

        rnn_load_W(STG, tid, 0, Wlo8, Whi8, n0);
        rnn_load_W(STG, tid, 1, Wlo8, Whi8, n0);
        rnn_load_W(STG, tid, 2, Wlo8, Whi8, n0);

        const float C1 = 1.f / 266338304.f;      // 1/(127 * 2^21)
        const float C2 = 1.f / 268435456.f;      // 1/2^28 = 1/(2^19 * 512)

#pragma unroll 1
        for (int t = 1; t < SEQ; t++) {
            if (t > 1) {
                if (tid == 0) {
                    const unsigned* slot = &g_bar[(t - 1) * 8 + grp];
                    unsigned v;
                    while (true) {
                        asm volatile("ld.acquire.gpu.global.u32 %0, [%1];"
                                     : "=r"(v) : "l"(slot) : "memory");
                        if (v >= GRPSZ) break;
                        __nanosleep(32);
                    }
                }
                __syncthreads();
            }

            const __half* Ahi = hhi + (size_t)(t - 1) * SLOT;
            const char*   H8  = h8g  + (size_t)(t - 1) * SLOT;
            const char*   L8  = lo8g + (size_t)(t - 1) * SLOT;
            rnn_load_A(STG, tid, 0, Ahi, H8, L8, m0);
            rnn_load_A(STG, tid, 1, Ahi, H8, L8, m0);
            rnn_load_A(STG, tid, 2, Ahi, H8, L8, m0);

            float    acc0[2][4];                 // main term, fp32 acc
            int32_t  ic1[2][4], ic2[2][4];       // corrections, s32 acc
#pragma unroll
            for (int j = 0; j < 2; j++)
#pragma unroll
                for (int q = 0; q < 4; q++) {
                    acc0[j][q] = 0.f; ic1[j][q] = 0; ic2[j][q] = 0;
                }

#pragma unroll 1
            for (int k0 = 0; k0 < 16; k0++) {
                wait_chunk(k0);
                __syncthreads();
                if (k0 + 3 < 16)
                    rnn_load_stage(STG, tid, k0 + 3, Ahi, H8, L8, Wlo8, Whi8, m0, n0);
                const uint32_t stg  = STG + (uint32_t)(k0 & 3) * 16384;
                const uint32_t pinc = PIN + (uint32_t)k0 * 8192;
                // ---- main term: fp16 x fp16 -> fp32 ----
#pragma unroll
                for (int kk = 0; kk < 4; kk++) {
                    uint32_t afh[4], bfh[4];
                    {
                        const int r0 = wm * 16 + (lane & 15);
                        const int c2 = (kk * 16 + (lane >> 4) * 8) * 2;
                        LDSM4(afh, stg + swz((uint32_t)(r0 * 128 + c2)));
                    }
                    {
                        const int r0 = wn * 16 + (lane & 7) + ((lane >> 4) << 3);
                        const int c2 = (kk * 16 + ((lane >> 3) & 1) * 8) * 2;
                        LDSM4(bfh, pinc + swz((uint32_t)(r0 * 128 + c2)));
                    }
                    MMA16816(acc0[0], afh, bfh[0], bfh[1]);
                    MMA16816(acc0[1], afh, bfh[2], bfh[3]);
                }
                // ---- corrections: s8 x s8 -> s32, K=32 per mma ----
#pragma unroll
                for (int k2 = 0; k2 < 2; k2++) {
                    uint32_t a8[4], al[4], bw0[2], bw1[2], bh0[2], bh1[2];
                    {
                        const int r0 = wm * 16 + (lane & 15);
                        const int cb = k2 * 32 + (lane >> 4) * 16;
                        const uint32_t off = swz64((uint32_t)(r0 * 64 + cb));
                        LDSM4(a8, stg + 4096 + off);
                        LDSM4(al, stg + 6144 + off);
                    }
                    {
                        const int rr = lane & 7;
                        const int cb = k2 * 32 + ((lane >> 3) & 1) * 16;
                        const uint32_t o0 =
                            swz64((uint32_t)((wn * 16 + rr) * 64 + cb));
                        const uint32_t o1 =
                            swz64((uint32_t)((wn * 16 + 8 + rr) * 64 + cb));
                        LDSM2(bw0, stg + 8192  + o0);
                        LDSM2(bw1, stg + 8192  + o1);
                        LDSM2(bh0, stg + 12288 + o0);
                        LDSM2(bh1, stg + 12288 + o1);
                    }
                    MMAS8(ic1[0], a8, bw0[0], bw0[1]);   // h8 * wlo8
                    MMAS8(ic1[1], a8, bw1[0], bw1[1]);
                    MMAS8(ic2[0], al, bh0[0], bh0[1]);   // lo8 * whi8
                    MMAS8(ic2[1], al, bh1[0], bh1[1]);
                }
            }

            if (t + 1 < SEQ) {
                rnn_load_W(STG, tid, 0, Wlo8, Whi8, n0);
                rnn_load_W(STG, tid, 1, Wlo8, Whi8, n0);
                rnn_load_W(STG, tid, 2, Wlo8, Whi8, n0);
            }

            const size_t mr0 = m0 + wm * 16 + g;
            const int xr0 = x[mr0 * SEQ + t];
            const int xr1 = x[(mr0 + 8) * SEQ + t];
            const float* Pr[2] = { P + (size_t)xr0 * HID, P + (size_t)xr1 * HID };
            __half* dhi = hhi  + (size_t)t * SLOT;
            __half* dlo = hlos + (size_t)t * SLOT;
            char*   dh8 = h8g  + (size_t)t * SLOT;
            char*   dl8 = lo8g + (size_t)t * SLOT;
#pragma unroll
            for (int nf = 0; nf < 2; nf++) {
                const int n = n0 + wn * 16 + nf * 8 + t4 * 2;
#pragma unroll
                for (int h2 = 0; h2 < 2; h2++) {
                    const size_t m = mr0 + h2 * 8;
                    float v0 = acc0[nf][h2 * 2] +
                               C1 * (float)ic1[nf][h2 * 2] +
                               C2 * (float)ic2[nf][h2 * 2] +
                               bb[nf].x + Pr[h2][n];
                    float v1 = acc0[nf][h2 * 2 + 1] +
                               C1 * (float)ic1[nf][h2 * 2 + 1] +
                               C2 * (float)ic2[nf][h2 * 2 + 1] +
                               bb[nf].y + Pr[h2][n + 1];
                    const float h0 = tanhf(v0), h1 = tanhf(v1);
                    const __half a0 = __float2half_rn(h0), a1 = __float2half_rn(h1);
                    const float f0 = __half2float(a0), f1 = __half2float(a1);
                    *(__half2*)(dhi + m * HID + n) = __halves2half2(a0, a1);
                    *(__half2*)(dlo + m * HID + n) =
                        __halves2half2(__float2half_rn((h0 - f0) * 32.f),
                                       __float2half_rn((h1 - f1) * 32.f));
                    // int8 splits for the next step's corrections
                    int q0 = __float2int_rn(h0 * 127.f);
                    int q1 = __float2int_rn(h1 * 127.f);
                    *(unsigned short*)(dh8 + m * HID + n) =
                        (unsigned short)((q0 & 0xFF) | ((q1 & 0xFF) << 8));
                    int l0 = __float2int_rn((h0 - f0) * 524288.f);
                    int l1 = __float2int_rn((h1 - f1) * 524288.f);
                    l0 = max(-127, min(127, l0));
                    l1 = max(-127, min(127, l1));
                    *(unsigned short*)(dl8 + m * HID + n) =
                        (unsigned short)((l0 & 0xFF) | ((l1 & 0xFF) << 8));
                }
            }

            __threadfence();
            __syncthreads();
            if (tid == 0) {
                unsigned* slot = &g_bar[t * 8 + grp];
                asm volatile("red.release.gpu.global.add.u32 [%0], %1;"
                             :: "l"(slot), "r"(1u) : "memory");
            }
        }
        return;
    }

    // ======================= fc consumer path (round-10, unchanged) ========
    const int cta = blockIdx.x - NCTA;
    const uint32_t FST = sb;
    const int wm = wid >> 1, wn = wid & 1;
    const int g = lane >> 2, t4 = lane & 3;

#pragma unroll 1
    for (int u = cta; u < 2 * SEQ; u += NFC) {
        const int t = u >> 1, bh = u & 1;

        if (t >= 1) {
            if (tid < 4) {
                const unsigned* slot = &g_bar[t * 8 + bh * 4 + tid];
                unsigned v;
                while (true) {
                    asm volatile("ld.acquire.gpu.global.u32 %0, [%1];"
                                 : "=r"(v) : "l"(slot) : "memory");
                    if (v >= GRPSZ) break;
                    __nanosleep(128);
                }
            }
        }
        __syncthreads();

        const __half* Ah = hhi  + (size_t)t * SLOT + (size_t)bh * 128 * HID;
        const __half* Al = hlos + (size_t)t * SLOT + (size_t)bh * 128 * HID;

        fc_load(FST, tid, 0, 0, Ah, Al, FChi, FClos);
        fc_load(FST, tid, 1, 1, Ah, Al, FChi, FClos);
        fc_load(FST, tid, 2, 2, Ah, Al, FChi, FClos);

        float    accA[2][8][4];
        uint32_t accBh[2][8][2];
#pragma unroll
        for (int i = 0; i < 2; i++)
#pragma unroll
            for (int j = 0; j < 8; j++) {
#pragma unroll
                for (int q = 0; q < 4; q++) accA[i][j][q] = 0.f;
                accBh[i][j][0] = 0u; accBh[i][j][1] = 0u;
            }

#pragma unroll 1
        for (int c = 0; c < 48; c++) {
            if (c < 46)       CP_WAIT2();
            else if (c == 46) CP_WAIT1();
            else              CP_WAIT0();
            __syncthreads();
            if (c + 3 < 48)
                fc_load(FST, tid, (c + 3) & 3, c + 3, Ah, Al, FChi, FClos);

            const uint32_t stg = FST + (uint32_t)(c & 3) * 32768;
            const bool mainseg = (c >> 4) == 0;
#pragma unroll
            for (int kk = 0; kk < 4; kk++) {
                uint32_t af[2][4], bf[4][4];
                {
                    const int r0 = wm * 32 + (lane & 15);
                    const int c2 = (kk * 16 + (lane >> 4) * 8) * 2;
#pragma unroll
                    for (int mf = 0; mf < 2; mf++)
                        LDSM4(af[mf], stg + swz((uint32_t)((r0 + mf * 16) * 128 + c2)));
                }
                {
                    const int r0 = wn * 64 + (lane & 7) + ((lane >> 4) << 3);
                    const int c2 = (kk * 16 + ((lane >> 3) & 1) * 8) * 2;
#pragma unroll
                    for (int np = 0; np < 4; np++)
                        LDSM4(bf[np], stg + 16384 +
                                      swz((uint32_t)((r0 + np * 16) * 128 + c2)));
                }
                if (mainseg) {
#pragma unroll
                    for (int mf = 0; mf < 2; mf++)
#pragma unroll
                        for (int np = 0; np < 4; np++) {
                            MMA16816(accA[mf][np * 2],     af[mf], bf[np][0], bf[np][1]);
                            MMA16816(accA[mf][np * 2 + 1], af[mf], bf[np][2], bf[np][3]);
                        }
                } else {
#pragma unroll
                    for (int mf = 0; mf < 2; mf++)
#pragma unroll
                        for (int np = 0; np < 4; np++) {
                            MMA16816H(accBh[mf][np * 2],     af[mf], bf[np][0], bf[np][1]);
                            MMA16816H(accBh[mf][np * 2 + 1], af[mf], bf[np][2], bf[np][3]);
                        }
                }
            }
        }

#pragma unroll
        for (int mf = 0; mf < 2; mf++) {
#pragma unroll
            for (int nf = 0; nf < 8; nf++) {
                const int n = wn * 64 + (nf >> 1) * 16 + (nf & 1) * 8 + t4 * 2;
                const float b0 = fcb[n], b1 = fcb[n + 1];
#pragma unroll
                for (int h2 = 0; h2 < 2; h2++) {
                    const int mloc = wm * 32 + mf * 16 + g + h2 * 8;
                    const size_t b = (size_t)bh * 128 + mloc;
                    const __half2 cb = *reinterpret_cast<const __half2*>(&accBh[mf][nf][h2]);
                    float2 o;
                    o.x = accA[mf][nf][h2 * 2]     + 0.03125f * __low2float(cb)  + b0;
                    o.y = accA[mf][nf][h2 * 2 + 1] + 0.03125f * __high2float(cb) + b1;
                    *(float2*)(outp + (b * SEQ + t) * VOCABN + n) = o;
                }
            }
        }
        __syncthreads();
    }
}

// ===========================================================================
// Generic streaming 3-split GEMM (P precompute only) — unchanged.
// ===========================================================================
template<int BM, int BN>
__device__ __forceinline__ void g3_load(
    uint32_t STG, int tid, int k0, size_t m0, int n0,
    const __half* __restrict__ Ahi, const __half* __restrict__ Alos,
    const __half* __restrict__ Bhi, const __half* __restrict__ Blos)
{
    constexpr int STAGE = (2 * BM + 2 * BN) * 128;
    const uint32_t stg = STG + (uint32_t)(k0 & 3) * STAGE;
#pragma unroll
    for (int i = 0; i < BM * 8 / 256; i++) {
        int id = tid + i * 256, r = id >> 3, cc = id & 7;
        int kb = k0 * 64 + cc * 8;
        uint32_t off = swz((uint32_t)(r * 128 + cc * 16));
        CP_ASYNC16(stg + off,            Ahi  + (m0 + r) * (size_t)HID + kb);
        CP_ASYNC16(stg + BM * 128 + off, Alos + (m0 + r) * (size_t)HID + kb);
    }
#pragma unroll
    for (int i = 0; i < BN * 8 / 256; i++) {
        int id = tid + i * 256, r = id >> 3, cc = id & 7;
        int kb = k0 * 64 + cc * 8;
        uint32_t off = swz((uint32_t)(r * 128 + cc * 16));
        CP_ASYNC16(stg + 2 * BM * 128 + off,            Bhi  + (size_t)(n0 + r) * HID + kb);
        CP_ASYNC16(stg + 2 * BM * 128 + BN * 128 + off, Blos + (size_t)(n0 + r) * HID + kb);
    }
    CP_COMMIT();
}

template<int BM, int BN, int WM, int WN>
__global__ __launch_bounds__(256, 1)
void k_g3(const __half* __restrict__ Ahi, const __half* __restrict__ Alos,
          const __half* __restrict__ Bhi, const __half* __restrict__ Blos,
          const float* __restrict__ bias, float* __restrict__ Cf)
{
    constexpr int TM = BM / WM, TN = BN / WN;
    constexpr int MF = TM / 16, NF2 = TN / 16;
    constexpr int STAGE = (2 * BM + 2 * BN) * 128;

    extern __shared__ char smem_raw[];
    const uint32_t sb = (smem_u32(smem_raw) + 1023u) & ~1023u;
    const int tid = threadIdx.x, wid = tid >> 5, lane = tid & 31;
    const int wm = wid / WN, wn = wid % WN;
    const int n0 = blockIdx.x * BN;
    const size_t m0 = (size_t)blockIdx.y * BM;

    float acc[3][MF][NF2 * 2][4];
#pragma unroll
    for (int s = 0; s < 3; s++)
#pragma unroll
        for (int i = 0; i < MF; i++)
#pragma unroll
            for (int j = 0; j < NF2 * 2; j++)
#pragma unroll
                for (int q = 0; q < 4; q++) acc[s][i][j][q] = 0.f;

    g3_load<BM, BN>(sb, tid, 0, m0, n0, Ahi, Alos, Bhi, Blos);
    g3_load<BM, BN>(sb, tid, 1, m0, n0, Ahi, Alos, Bhi, Blos);
    g3_load<BM, BN>(sb, tid, 2, m0, n0, Ahi, Alos, Bhi, Blos);

#pragma unroll 1
    for (int k0 = 0; k0 < 16; k0++) {
        wait_chunk(k0);
        __syncthreads();
        if (k0 + 3 < 16)
            g3_load<BM, BN>(sb, tid, k0 + 3, m0, n0, Ahi, Alos, Bhi, Blos);
        const uint32_t stg = sb + (uint32_t)(k0 & 3) * STAGE;
        const uint32_t aH = stg, aL = stg + BM * 128;
        const uint32_t bH = stg + 2 * BM * 128, bL = bH + BN * 128;
#pragma unroll
        for (int kk = 0; kk < 4; kk++) {
            uint32_t afh[MF][4], afl[MF][4], bfh[NF2][4], bfl[NF2][4];
            {
                const int r0 = wm * TM + (lane & 15);
                const int c2 = (kk * 16 + (lane >> 4) * 8) * 2;
#pragma unroll
                for (int mf = 0; mf < MF; mf++) {
                    uint32_t off = swz((uint32_t)((r0 + mf * 16) * 128 + c2));
                    LDSM4(afh[mf], aH + off);
                    LDSM4(afl[mf], aL + off);
                }
            }
            {
                const int r0 = wn * TN + (lane & 7) + ((lane >> 4) << 3);
                const int c2 = (kk * 16 + ((lane >> 3) & 1) * 8) * 2;
#pragma unroll
                for (int np = 0; np < NF2; np++) {
                    uint32_t off = swz((uint32_t)((r0 + np * 16) * 128 + c2));
                    LDSM4(bfh[np], bH + off);
                    LDSM4(bfl[np], bL + off);
                }
            }
#pragma unroll
            for (int mf = 0; mf < MF; mf++)
#pragma unroll
                for (int np = 0; np < NF2; np++) {
                    MMA16816(acc[0][mf][np * 2],     afh[mf], bfh[np][0], bfh[np][1]);
                    MMA16816(acc[0][mf][np * 2 + 1], afh[mf], bfh[np][2], bfh[np][3]);
                    MMA16816(acc[1][mf][np * 2],     afh[mf], bfl[np][0], bfl[np][1]);
                    MMA16816(acc[1][mf][np * 2 + 1], afh[mf], bfl[np][2], bfl[np][3]);
                    MMA16816(acc[2][mf][np * 2],     afl[mf], bfh[np][0], bfh[np][1]);
                    MMA16816(acc[2][mf][np * 2 + 1], afl[mf], bfh[np][2], bfh[np][3]);
                }
        }
    }

    const int g = lane >> 2, t4 = lane & 3;
#pragma unroll
    for (int mf = 0; mf < MF; mf++) {
#pragma unroll
        for (int nf = 0; nf < NF2 * 2; nf++) {
            const int n = n0 + wn * TN + (nf >> 1) * 16 + (nf & 1) * 8 + t4 * 2;
            const float b0 = bias[n], b1 = bias[n + 1];
#pragma unroll
            for (int h2 = 0; h2 < 2; h2++) {
                const size_t m = m0 + wm * TM + mf * 16 + g + h2 * 8;
                float2 o;
                o.x = acc[0][mf][nf][h2 * 2] +
                      0.03125f * (acc[1][mf][nf][h2 * 2] + acc[2][mf][nf][h2 * 2]) + b0;
                o.y = acc[0][mf][nf][h2 * 2 + 1] +
                      0.03125f * (acc[1][mf][nf][h2 * 2 + 1] + acc[2][mf][nf][h2 * 2 + 1]) + b1;
                *(float2*)(Cf + m * HID + n) = o;
            }
        }
    }
}

// ---------------- small kernels ----------------
__global__ __launch_bounds__(256)
void k_split(const float* __restrict__ w, __half* __restrict__ hi,
             __half* __restrict__ los, int n)
{
    int i = blockIdx.x * 256 + threadIdx.x;
    if (i >= n) return;
    float v = w[i];
    __half h = __float2half_rn(v);
    hi[i]  = h;
    los[i] = __float2half_rn((v - __half2float(h)) * 32.f);
}

// Whh split: fp16 hi + int8 wlo (scale 2^21) + int8 whi (scale 512)
__global__ __launch_bounds__(256)
void k_split_whh(const float* __restrict__ w, __half* __restrict__ hi,
                 char* __restrict__ wlo8, char* __restrict__ whi8, int n)
{
    int i = blockIdx.x * 256 + threadIdx.x;
    if (i >= n) return;
    float v = w[i];
    __half h = __float2half_rn(v);
    hi[i] = h;
    float lo = v - __half2float(h);
    int q = __float2int_rn(lo * 2097152.f);
    wlo8[i] = (char)max(-127, min(127, q));
    int p = __float2int_rn(__half2float(h) * 512.f);
    whi8[i] = (char)max(-127, min(127, p));
}

__global__ __launch_bounds__(256)
void k_step0(const int* __restrict__ x, const float* __restrict__ P,
             const float* __restrict__ bias, __half* __restrict__ hhi,
             __half* __restrict__ hlos, char* __restrict__ h8,
             char* __restrict__ lo8)
{
    int idx = blockIdx.x * 256 + threadIdx.x;
    int b = idx >> 10, n = idx & (HID - 1);
    float h = tanhf(P[(size_t)x[b * SEQ] * HID + n] + bias[n]);
    __half a = __float2half_rn(h);
    float f = __half2float(a);
    hhi[idx]  = a;
    hlos[idx] = __float2half_rn((h - f) * 32.f);
    h8[idx]   = (char)__float2int_rn(h * 127.f);
    int l = __float2int_rn((h - f) * 524288.f);
    lo8[idx]  = (char)max(-127, min(127, l));
}

__global__ void k_zero_bar() { g_bar[blockIdx.x * 256 + threadIdx.x] = 0; }

__global__ __launch_bounds__(256)
void k_hidden(const __half* __restrict__ hi, const __half* __restrict__ los,
              float* __restrict__ dst)
{
    int i = blockIdx.x * 256 + threadIdx.x;
    dst[i] = __half2float(hi[i]) + __half2float(los[i]) * 0.03125f;
}

extern "C" void kernel_launch(void* const* d_in, const int* in_sizes, int n_in,
                              void* d_out, int out_size)
{
    const int*   x     = (const int*)  d_in[0];
    const float* embed = (const float*)d_in[1];
    const float* Wxh_w = (const float*)d_in[2];
    const float* Wxh_b = (const float*)d_in[3];
    const float* Whh_w = (const float*)d_in[4];
    const float* Whh_b = (const float*)d_in[5];
    const float* fc_w  = (const float*)d_in[6];
    const float* fc_b  = (const float*)d_in[7];
    float* outp = (float*)d_out;

    float* P;
    __half *hhi, *hlos, *whhhi, *wxhhi, *wxhlos, *embhi, *emblos, *fchi, *fclos;
    char *h8, *lo8, *wlo8, *whi8;
    cudaGetSymbolAddress((void**)&P,      g_P);
    cudaGetSymbolAddress((void**)&hhi,    g_hhi);
    cudaGetSymbolAddress((void**)&hlos,   g_hlos);
    cudaGetSymbolAddress((void**)&h8,     g_h8);
    cudaGetSymbolAddress((void**)&lo8,    g_lo8);
    cudaGetSymbolAddress((void**)&whhhi,  g_whhhi);
    cudaGetSymbolAddress((void**)&wlo8,   g_wlo8);
    cudaGetSymbolAddress((void**)&whi8,   g_whi8);
    cudaGetSymbolAddress((void**)&wxhhi,  g_wxhhi);
    cudaGetSymbolAddress((void**)&wxhlos, g_wxhlos);
    cudaGetSymbolAddress((void**)&embhi,  g_embhi);
    cudaGetSymbolAddress((void**)&emblos, g_emblos);
    cudaGetSymbolAddress((void**)&fchi,   g_fchi);
    cudaGetSymbolAddress((void**)&fclos,  g_fclos);

    const int SM_P   = (2 * 32 + 2 * 64) * 128 * 4 + 1024;    //  97 KB
    const int SM_RNN = 131072 + 4 * 16384 + 1024;             // 193 KB
    cudaFuncSetAttribute(k_g3<32, 64, 2, 4>,
                         cudaFuncAttributeMaxDynamicSharedMemorySize, SM_P);
    cudaFuncSetAttribute(k_fused,
                         cudaFuncAttributeMaxDynamicSharedMemorySize, SM_RNN);

    const size_t SLOT = (size_t)BATCHN * HID;

    // 0) operand splits
    k_split_whh<<<(HID * HID) / 256, 256>>>(Whh_w, whhhi, wlo8, whi8, HID * HID);
    k_split<<<(HID * HID) / 256, 256>>>(Wxh_w, wxhhi, wxhlos, HID * HID);
    k_split<<<(VOCABN * HID) / 256, 256>>>(fc_w, fchi, fclos, VOCABN * HID);
    k_split<<<(VOCABN * HID) / 256, 256>>>(embed, embhi, emblos, VOCABN * HID);

    // 1) P = embed @ Wxh^T + bxh
    k_g3<32, 64, 2, 4><<<dim3(HID / 64, VOCABN / 32), 256, SM_P>>>(
        embhi, emblos, wxhhi, wxhlos, Wxh_b, P);

    // 2) t = 0
    k_step0<<<(BATCHN * HID) / 256, 256>>>(x, P, Whh_b, hhi, hlos, h8, lo8);

    // 3) reset barriers, then fused persistent recurrence + fc consumers
    k_zero_bar<<<8, 256>>>();
    k_fused<<<NCTA + NFC, 256, SM_RNN>>>(whhhi, wlo8, whi8, Whh_b, P, x,
                                         hhi, hlos, h8, lo8,
                                         fchi, fclos, fc_b, outp);

    // 4) hidden = h_{S-1}
    k_hidden<<<(BATCHN * HID) / 256, 256>>>(
        hhi + (size_t)(SEQ - 1) * SLOT, hlos + (size_t)(SEQ - 1) * SLOT,
        outp + (size_t)BATCHN * SEQ * VOCABN);
}

// round 12
// speedup vs baseline: 1.8103x; 1.8103x over previous
#include <cuda_runtime.h>
#include <cuda_fp16.h>
#include <math.h>
#include <stdint.h>

#define VOCABN 128
#define HID    1024
#define BATCHN 256
#define SEQ    256
#define NCTA   128     // recurrence CTAs
#define NFC    20      // fc consumer CTAs
#define GRPSZ  16u

// ---------------- device scratch (no allocations allowed) ----------------
__device__ float    g_P[VOCABN * HID];
__device__ __half   g_hhi [(size_t)SEQ * BATCHN * HID];
__device__ __half   g_hlos[(size_t)SEQ * BATCHN * HID];
__device__ __half   g_whhhi[HID * HID], g_whhlos[HID * HID];
__device__ __half   g_wxhhi[HID * HID], g_wxhlos[HID * HID];
__device__ __half   g_embhi[VOCABN * HID], g_emblos[VOCABN * HID];
__device__ __half   g_fchi[VOCABN * HID],  g_fclos[VOCABN * HID];
__device__ unsigned g_bar[SEQ * 8];                  // per-(step, m-group) counters

// ---------------- PTX helpers ----------------
__device__ __forceinline__ uint32_t smem_u32(const void* p) {
    uint32_t a;
    asm("{ .reg .u64 t; cvta.to.shared.u64 t, %1; cvt.u32.u64 %0, t; }" : "=r"(a) : "l"(p));
    return a;
}
__device__ __forceinline__ uint32_t swz(uint32_t o) { return o ^ ((o >> 3) & 0x70); }

#define CP_ASYNC16(dst, src) \
    asm volatile("cp.async.cg.shared.global [%0], [%1], 16;" :: "r"(dst), "l"(src) : "memory")
#define CP_COMMIT() asm volatile("cp.async.commit_group;" ::: "memory")
#define CP_WAIT2()  asm volatile("cp.async.wait_group 2;" ::: "memory")
#define CP_WAIT1()  asm volatile("cp.async.wait_group 1;" ::: "memory")
#define CP_WAIT0()  asm volatile("cp.async.wait_group 0;" ::: "memory")

#define LDSM4(r, addr)                                                            \
    asm volatile("ldmatrix.sync.aligned.m8n8.x4.shared.b16 {%0,%1,%2,%3}, [%4];"  \
        : "=r"((r)[0]), "=r"((r)[1]), "=r"((r)[2]), "=r"((r)[3]) : "r"(addr))

// fp32-accumulate mma (main term — exact)
#define MMA16816(c, a, b0, b1)                                                    \
    asm volatile("mma.sync.aligned.m16n8k16.row.col.f32.f16.f16.f32 "             \
        "{%0,%1,%2,%3},{%4,%5,%6,%7},{%8,%9},{%0,%1,%2,%3};"                      \
        : "+f"((c)[0]), "+f"((c)[1]), "+f"((c)[2]), "+f"((c)[3])                   \
        : "r"((a)[0]), "r"((a)[1]), "r"((a)[2]), "r"((a)[3]), "r"(b0), "r"(b1))

// fp16-accumulate mma (correction terms)
#define MMA16816H(c, a, b0, b1)                                                   \
    asm volatile("mma.sync.aligned.m16n8k16.row.col.f16.f16.f16.f16 "             \
        "{%0,%1},{%2,%3,%4,%5},{%6,%7},{%0,%1};"                                  \
        : "+r"((c)[0]), "+r"((c)[1])                                              \
        : "r"((a)[0]), "r"((a)[1]), "r"((a)[2]), "r"((a)[3]), "r"(b0), "r"(b1))

// ===========================================================================
// RNN loaders. Big chunk = K=128 = two 16KB halves, slot = bk % 3 (32KB each).
// Half layout: [Ahi fp16 4KB | Alo fp16 4KB | Wlos fp16 8KB], all SW128.
// ===========================================================================
__device__ __forceinline__ void rnn_load_W2(
    uint32_t STG, int tid, int bk, const __half* __restrict__ Wlos, int n0)
{
    const uint32_t stg0 = STG + (uint32_t)(bk % 3) * 32768;
    const int r = tid >> 3, cc = tid & 7;
#pragma unroll
    for (int sub = 0; sub < 2; sub++) {
        const int kb = (bk * 2 + sub) * 64 + cc * 8;
        const uint32_t stg = stg0 + (uint32_t)sub * 16384;
        CP_ASYNC16(stg + 8192 + swz((uint32_t)(r * 128 + cc * 16)),
                   Wlos + (size_t)(n0 + r) * HID + kb);
        CP_ASYNC16(stg + 8192 + swz((uint32_t)((r + 32) * 128 + cc * 16)),
                   Wlos + (size_t)(n0 + r + 32) * HID + kb);
    }
    CP_COMMIT();
}

__device__ __forceinline__ void rnn_load_A2(
    uint32_t STG, int tid, int bk,
    const __half* __restrict__ Ahi, const __half* __restrict__ Alo, size_t m0)
{
    const uint32_t stg0 = STG + (uint32_t)(bk % 3) * 32768;
    const int r = tid >> 3, cc = tid & 7;
    const uint32_t off = swz((uint32_t)(r * 128 + cc * 16));
#pragma unroll
    for (int sub = 0; sub < 2; sub++) {
        const int kb = (bk * 2 + sub) * 64 + cc * 8;
        const uint32_t stg = stg0 + (uint32_t)sub * 16384;
        CP_ASYNC16(stg + off,        Ahi + (m0 + r) * (size_t)HID + kb);
        CP_ASYNC16(stg + 4096 + off, Alo + (m0 + r) * (size_t)HID + kb);
    }
    CP_COMMIT();
}

__device__ __forceinline__ void rnn_load_full2(
    uint32_t STG, int tid, int bk,
    const __half* __restrict__ Ahi, const __half* __restrict__ Alo,
    const __half* __restrict__ Wlos, size_t m0, int n0)
{
    const uint32_t stg0 = STG + (uint32_t)(bk % 3) * 32768;
    const int r = tid >> 3, cc = tid & 7;
    const uint32_t off = swz((uint32_t)(r * 128 + cc * 16));
#pragma unroll
    for (int sub = 0; sub < 2; sub++) {
        const int kb = (bk * 2 + sub) * 64 + cc * 8;
        const uint32_t stg = stg0 + (uint32_t)sub * 16384;
        CP_ASYNC16(stg + off,        Ahi + (m0 + r) * (size_t)HID + kb);
        CP_ASYNC16(stg + 4096 + off, Alo + (m0 + r) * (size_t)HID + kb);
        CP_ASYNC16(stg + 8192 + off, Wlos + (size_t)(n0 + r) * HID + kb);
        CP_ASYNC16(stg + 8192 + swz((uint32_t)((r + 32) * 128 + cc * 16)),
                   Wlos + (size_t)(n0 + r + 32) * HID + kb);
    }
    CP_COMMIT();
}

// ---- fc consumer loader (unchanged from round 10) ----
__device__ __forceinline__ void fc_load(
    uint32_t FST, int tid, int slot, int c,
    const __half* __restrict__ Ahi, const __half* __restrict__ Alos,
    const __half* __restrict__ Bhi, const __half* __restrict__ Blos)
{
    const int seg = c >> 4;
    const __half* A = (seg == 2) ? Alos : Ahi;
    const __half* B = (seg == 1) ? Blos : Bhi;
    const uint32_t stg = FST + (uint32_t)slot * 32768;
#pragma unroll
    for (int i = 0; i < 4; i++) {
        int id = tid + i * 256, r = id >> 3;
        uint32_t off = swz((uint32_t)(r * 128 + (id & 7) * 16));
        CP_ASYNC16(stg + off, A + (size_t)r * HID + (c & 15) * 64 + (id & 7) * 8);
    }
#pragma unroll
    for (int i = 0; i < 4; i++) {
        int id = tid + i * 256, r = id >> 3;
        uint32_t off = swz((uint32_t)(r * 128 + (id & 7) * 16));
        CP_ASYNC16(stg + 16384 + off, B + (size_t)r * HID + (c & 15) * 64 + (id & 7) * 8);
    }
    CP_COMMIT();
}

// ===========================================================================
// Fused persistent kernel: CTAs 0..127 recurrence (8 big chunks, 3 stages),
// CTAs 128..147 fc consumers. Hidden output fused into t=255 epilogue.
// ===========================================================================
__global__ __launch_bounds__(256, 1)
void k_fused(const __half* __restrict__ Whi, const __half* __restrict__ Wlos,
             const float* __restrict__ bias, const float* __restrict__ P,
             const int* __restrict__ x,
             __half* __restrict__ hhi, __half* __restrict__ hlos,
             const __half* __restrict__ FChi, const __half* __restrict__ FClos,
             const float* __restrict__ fcb, float* __restrict__ outp)
{
    extern __shared__ char smem_raw[];
    const uint32_t sb  = (smem_u32(smem_raw) + 1023u) & ~1023u;
    const int tid = threadIdx.x;
    const int wid = tid >> 5, lane = tid & 31;
    const size_t SLOT = (size_t)BATCHN * HID;

    if (blockIdx.x < NCTA) {
        // =================== RNN path ===================
        const uint32_t PIN = sb;                 // 16 x 8KB pinned Whi
        const uint32_t STG = sb + 131072;        // 3 x 32KB stages
        const int wm  = wid >> 2, wn = wid & 3;
        const int g   = lane >> 2, t4 = lane & 3;
        const int grp = blockIdx.x >> 4;
        const size_t m0 = (size_t)grp * 32;
        const int    n0 = (blockIdx.x & 15) * 64;

        {
            const int r = tid >> 3, cc = tid & 7;
#pragma unroll 1
            for (int k0 = 0; k0 < 16; k0++) {
#pragma unroll
                for (int p = 0; p < 2; p++) {
                    int rr = r + p * 32;
                    CP_ASYNC16(PIN + k0 * 8192 + swz((uint32_t)(rr * 128 + cc * 16)),
                               Whi + (size_t)(n0 + rr) * HID + k0 * 64 + cc * 8);
                }
            }
            CP_COMMIT(); CP_WAIT0();
        }
        __syncthreads();

        float2 bb[2];
#pragma unroll
        for (int nf = 0; nf < 2; nf++) {
            int n = n0 + wn * 16 + nf * 8 + t4 * 2;
            bb[nf].x = bias[n]; bb[nf].y = bias[n + 1];
        }

        // W prefetch for chunk 0 of the first step (slot 0)
        rnn_load_W2(STG, tid, 0, Wlos, n0);

#pragma unroll 1
        for (int t = 1; t < SEQ; t++) {
            if (t > 1) {
                if (tid == 0) {
                    const unsigned* slot = &g_bar[(t - 1) * 8 + grp];
                    unsigned v;
                    while (true) {
                        asm volatile("ld.acquire.gpu.global.u32 %0, [%1];"
                                     : "=r"(v) : "l"(slot) : "memory");
                        if (v >= GRPSZ) break;
                        __nanosleep(32);
                    }
                }
                __syncthreads();
            }

            const __half* Ahi = hhi  + (size_t)(t - 1) * SLOT;
            const __half* Alo = hlos + (size_t)(t - 1) * SLOT;
            // fill: A of chunk 0 (W already prefetched), full chunk 1
            rnn_load_A2(STG, tid, 0, Ahi, Alo, m0);
            rnn_load_full2(STG, tid, 1, Ahi, Alo, Wlos, m0, n0);

            float    acc0[2][4];                 // main term, fp32 acc
            uint32_t ach1[2][2], ach2[2][2];     // corrections, fp16 acc
#pragma unroll
            for (int j = 0; j < 2; j++) {
#pragma unroll
                for (int q = 0; q < 4; q++) acc0[j][q] = 0.f;
                ach1[j][0] = 0u; ach1[j][1] = 0u;
                ach2[j][0] = 0u; ach2[j][1] = 0u;
            }

#pragma unroll 1
            for (int k = 0; k < 8; k++) {
                if (k < 7) CP_WAIT1(); else CP_WAIT0();
                __syncthreads();
                if (k + 2 < 8)
                    rnn_load_full2(STG, tid, k + 2, Ahi, Alo, Wlos, m0, n0);
                const uint32_t stg0 = STG + (uint32_t)(k % 3) * 32768;
#pragma unroll
                for (int sub = 0; sub < 2; sub++) {
                    const uint32_t stg  = stg0 + (uint32_t)sub * 16384;
                    const uint32_t pinc = PIN + (uint32_t)(k * 2 + sub) * 8192;
#pragma unroll
                    for (int kk = 0; kk < 4; kk++) {
                        uint32_t afh[4], afl[4], bfh[4], bfl[4];
                        {
                            const int r0 = wm * 16 + (lane & 15);
                            const int c2 = (kk * 16 + (lane >> 4) * 8) * 2;
                            const uint32_t off = swz((uint32_t)(r0 * 128 + c2));
                            LDSM4(afh, stg + off);
                            LDSM4(afl, stg + 4096 + off);
                        }
                        {
                            const int r0 = wn * 16 + (lane & 7) + ((lane >> 4) << 3);
                            const int c2 = (kk * 16 + ((lane >> 3) & 1) * 8) * 2;
                            const uint32_t off = swz((uint32_t)(r0 * 128 + c2));
                            LDSM4(bfh, pinc + off);
                            LDSM4(bfl, stg + 8192 + off);
                        }
                        MMA16816(acc0[0], afh, bfh[0], bfh[1]);   // hi*hi
                        MMA16816(acc0[1], afh, bfh[2], bfh[3]);
                        MMA16816H(ach1[0], afh, bfl[0], bfl[1]);  // hi*wlo
                        MMA16816H(ach1[1], afh, bfl[2], bfl[3]);
                        MMA16816H(ach2[0], afl, bfh[0], bfh[1]);  // lo*whi
                        MMA16816H(ach2[1], afl, bfh[2], bfh[3]);
                    }
                }
            }

            // W prefetch chunk 0 of next step: slot 0 = chunk 6's slot,
            // freed by the sync at top of iter 7 -> safe here.
            if (t + 1 < SEQ)
                rnn_load_W2(STG, tid, 0, Wlos, n0);

            const size_t mr0 = m0 + wm * 16 + g;
            const int xr0 = x[mr0 * SEQ + t];
            const int xr1 = x[(mr0 + 8) * SEQ + t];
            const float* Pr[2] = { P + (size_t)xr0 * HID, P + (size_t)xr1 * HID };
            __half* dhi = hhi  + (size_t)t * SLOT;
            __half* dlo = hlos + (size_t)t * SLOT;
            float* hid = outp + (size_t)BATCHN * SEQ * VOCABN;
#pragma unroll
            for (int nf = 0; nf < 2; nf++) {
                const int n = n0 + wn * 16 + nf * 8 + t4 * 2;
#pragma unroll
                for (int h2 = 0; h2 < 2; h2++) {
                    const size_t m = mr0 + h2 * 8;
                    const __half2 c1 = *reinterpret_cast<const __half2*>(&ach1[nf][h2]);
                    const __half2 c2 = *reinterpret_cast<const __half2*>(&ach2[nf][h2]);
                    float v0 = acc0[nf][h2 * 2] +
                               0.03125f * (__low2float(c1)  + __low2float(c2)) +
                               bb[nf].x + Pr[h2][n];
                    float v1 = acc0[nf][h2 * 2 + 1] +
                               0.03125f * (__high2float(c1) + __high2float(c2)) +
                               bb[nf].y + Pr[h2][n + 1];
                    const float h0 = tanhf(v0), h1 = tanhf(v1);
                    const __half a0 = __float2half_rn(h0), a1 = __float2half_rn(h1);
                    const float f0 = __half2float(a0), f1 = __half2float(a1);
                    *(__half2*)(dhi + m * HID + n) = __halves2half2(a0, a1);
                    *(__half2*)(dlo + m * HID + n) =
                        __halves2half2(__float2half_rn((h0 - f0) * 32.f),
                                       __float2half_rn((h1 - f1) * 32.f));
                    if (t == SEQ - 1) {            // fused hidden output (exact fp32)
                        float2 o; o.x = h0; o.y = h1;
                        *(float2*)(hid + m * HID + n) = o;
                    }
                }
            }

            __threadfence();
            __syncthreads();
            if (tid == 0) {
                unsigned* slot = &g_bar[t * 8 + grp];
                asm volatile("red.release.gpu.global.add.u32 [%0], %1;"
                             :: "l"(slot), "r"(1u) : "memory");
            }
        }
        return;
    }

    // ======================= fc consumer path (round-10, unchanged) ========
    const int cta = blockIdx.x - NCTA;
    const uint32_t FST = sb;                       // 4 stages x 32KB
    const int wm = wid >> 1, wn = wid & 1;
    const int g = lane >> 2, t4 = lane & 3;

#pragma unroll 1
    for (int u = cta; u < 2 * SEQ; u += NFC) {
        const int t = u >> 1, bh = u & 1;

        if (t >= 1) {
            if (tid < 4) {
                const unsigned* slot = &g_bar[t * 8 + bh * 4 + tid];
                unsigned v;
                while (true) {
                    asm volatile("ld.acquire.gpu.global.u32 %0, [%1];"
                                 : "=r"(v) : "l"(slot) : "memory");
                    if (v >= GRPSZ) break;
                    __nanosleep(128);
                }
            }
        }
        __syncthreads();

        const __half* Ah = hhi  + (size_t)t * SLOT + (size_t)bh * 128 * HID;
        const __half* Al = hlos + (size_t)t * SLOT + (size_t)bh * 128 * HID;

        fc_load(FST, tid, 0, 0, Ah, Al, FChi, FClos);
        fc_load(FST, tid, 1, 1, Ah, Al, FChi, FClos);
        fc_load(FST, tid, 2, 2, Ah, Al, FChi, FClos);

        float    accA[2][8][4];
        uint32_t accBh[2][8][2];
#pragma unroll
        for (int i = 0; i < 2; i++)
#pragma unroll
            for (int j = 0; j < 8; j++) {
#pragma unroll
                for (int q = 0; q < 4; q++) accA[i][j][q] = 0.f;
                accBh[i][j][0] = 0u; accBh[i][j][1] = 0u;
            }

#pragma unroll 1
        for (int c = 0; c < 48; c++) {
            if (c < 46)       CP_WAIT2();
            else if (c == 46) CP_WAIT1();
            else              CP_WAIT0();
            __syncthreads();
            if (c + 3 < 48)
                fc_load(FST, tid, (c + 3) & 3, c + 3, Ah, Al, FChi, FClos);

            const uint32_t stg = FST + (uint32_t)(c & 3) * 32768;
            const bool mainseg = (c >> 4) == 0;
#pragma unroll
            for (int kk = 0; kk < 4; kk++) {
                uint32_t af[2][4], bf[4][4];
                {
                    const int r0 = wm * 32 + (lane & 15);
                    const int c2 = (kk * 16 + (lane >> 4) * 8) * 2;
#pragma unroll
                    for (int mf = 0; mf < 2; mf++)
                        LDSM4(af[mf], stg + swz((uint32_t)((r0 + mf * 16) * 128 + c2)));
                }
                {
                    const int r0 = wn * 64 + (lane & 7) + ((lane >> 4) << 3);
                    const int c2 = (kk * 16 + ((lane >> 3) & 1) * 8) * 2;
#pragma unroll
                    for (int np = 0; np < 4; np++)
                        LDSM4(bf[np], stg + 16384 +
                                      swz((uint32_t)((r0 + np * 16) * 128 + c2)));
                }
                if (mainseg) {
#pragma unroll
                    for (int mf = 0; mf < 2; mf++)
#pragma unroll
                        for (int np = 0; np < 4; np++) {
                            MMA16816(accA[mf][np * 2],     af[mf], bf[np][0], bf[np][1]);
                            MMA16816(accA[mf][np * 2 + 1], af[mf], bf[np][2], bf[np][3]);
                        }
                } else {
#pragma unroll
                    for (int mf = 0; mf < 2; mf++)
#pragma unroll
                        for (int np = 0; np < 4; np++) {
                            MMA16816H(accBh[mf][np * 2],     af[mf], bf[np][0], bf[np][1]);
                            MMA16816H(accBh[mf][np * 2 + 1], af[mf], bf[np][2], bf[np][3]);
                        }
                }
            }
        }

#pragma unroll
        for (int mf = 0; mf < 2; mf++) {
#pragma unroll
            for (int nf = 0; nf < 8; nf++) {
                const int n = wn * 64 + (nf >> 1) * 16 + (nf & 1) * 8 + t4 * 2;
                const float b0 = fcb[n], b1 = fcb[n + 1];
#pragma unroll
                for (int h2 = 0; h2 < 2; h2++) {
                    const int mloc = wm * 32 + mf * 16 + g + h2 * 8;
                    const size_t b = (size_t)bh * 128 + mloc;
                    const __half2 cb = *reinterpret_cast<const __half2*>(&accBh[mf][nf][h2]);
                    float2 o;
                    o.x = accA[mf][nf][h2 * 2]     + 0.03125f * __low2float(cb)  + b0;
                    o.y = accA[mf][nf][h2 * 2 + 1] + 0.03125f * __high2float(cb) + b1;
                    *(float2*)(outp + (b * SEQ + t) * VOCABN + n) = o;
                }
            }
        }
        __syncthreads();
    }
}

// ===========================================================================
// Generic streaming 3-split GEMM (P precompute only) — unchanged.
// ===========================================================================
__device__ __forceinline__ void wait_chunk(int k0) {
    if (k0 < 14)       CP_WAIT2();
    else if (k0 == 14) CP_WAIT1();
    else               CP_WAIT0();
}

template<int BM, int BN>
__device__ __forceinline__ void g3_load(
    uint32_t STG, int tid, int k0, size_t m0, int n0,
    const __half* __restrict__ Ahi, const __half* __restrict__ Alos,
    const __half* __restrict__ Bhi, const __half* __restrict__ Blos)
{
    constexpr int STAGE = (2 * BM + 2 * BN) * 128;
    const uint32_t stg = STG + (uint32_t)(k0 & 3) * STAGE;
#pragma unroll
    for (int i = 0; i < BM * 8 / 256; i++) {
        int id = tid + i * 256, r = id >> 3, cc = id & 7;
        int kb = k0 * 64 + cc * 8;
        uint32_t off = swz((uint32_t)(r * 128 + cc * 16));
        CP_ASYNC16(stg + off,            Ahi  + (m0 + r) * (size_t)HID + kb);
        CP_ASYNC16(stg + BM * 128 + off, Alos + (m0 + r) * (size_t)HID + kb);
    }
#pragma unroll
    for (int i = 0; i < BN * 8 / 256; i++) {
        int id = tid + i * 256, r = id >> 3, cc = id & 7;
        int kb = k0 * 64 + cc * 8;
        uint32_t off = swz((uint32_t)(r * 128 + cc * 16));
        CP_ASYNC16(stg + 2 * BM * 128 + off,            Bhi  + (size_t)(n0 + r) * HID + kb);
        CP_ASYNC16(stg + 2 * BM * 128 + BN * 128 + off, Blos + (size_t)(n0 + r) * HID + kb);
    }
    CP_COMMIT();
}

template<int BM, int BN, int WM, int WN>
__global__ __launch_bounds__(256, 1)
void k_g3(const __half* __restrict__ Ahi, const __half* __restrict__ Alos,
          const __half* __restrict__ Bhi, const __half* __restrict__ Blos,
          const float* __restrict__ bias, float* __restrict__ Cf)
{
    constexpr int TM = BM / WM, TN = BN / WN;
    constexpr int MF = TM / 16, NF2 = TN / 16;
    constexpr int STAGE = (2 * BM + 2 * BN) * 128;

    extern __shared__ char smem_raw[];
    const uint32_t sb = (smem_u32(smem_raw) + 1023u) & ~1023u;
    const int tid = threadIdx.x, wid = tid >> 5, lane = tid & 31;
    const int wm = wid / WN, wn = wid % WN;
    const int n0 = blockIdx.x * BN;
    const size_t m0 = (size_t)blockIdx.y * BM;

    float acc[3][MF][NF2 * 2][4];
#pragma unroll
    for (int s = 0; s < 3; s++)
#pragma unroll
        for (int i = 0; i < MF; i++)
#pragma unroll
            for (int j = 0; j < NF2 * 2; j++)
#pragma unroll
                for (int q = 0; q < 4; q++) acc[s][i][j][q] = 0.f;

    g3_load<BM, BN>(sb, tid, 0, m0, n0, Ahi, Alos, Bhi, Blos);
    g3_load<BM, BN>(sb, tid, 1, m0, n0, Ahi, Alos, Bhi, Blos);
    g3_load<BM, BN>(sb, tid, 2, m0, n0, Ahi, Alos, Bhi, Blos);

#pragma unroll 1
    for (int k0 = 0; k0 < 16; k0++) {
        wait_chunk(k0);
        __syncthreads();
        if (k0 + 3 < 16)
            g3_load<BM, BN>(sb, tid, k0 + 3, m0, n0, Ahi, Alos, Bhi, Blos);
        const uint32_t stg = sb + (uint32_t)(k0 & 3) * STAGE;
        const uint32_t aH = stg, aL = stg + BM * 128;
        const uint32_t bH = stg + 2 * BM * 128, bL = bH + BN * 128;
#pragma unroll
        for (int kk = 0; kk < 4; kk++) {
            uint32_t afh[MF][4], afl[MF][4], bfh[NF2][4], bfl[NF2][4];
            {
                const int r0 = wm * TM + (lane & 15);
                const int c2 = (kk * 16 + (lane >> 4) * 8) * 2;
#pragma unroll
                for (int mf = 0; mf < MF; mf++) {
                    uint32_t off = swz((uint32_t)((r0 + mf * 16) * 128 + c2));
                    LDSM4(afh[mf], aH + off);
                    LDSM4(afl[mf], aL + off);
                }
            }
            {
                const int r0 = wn * TN + (lane & 7) + ((lane >> 4) << 3);
                const int c2 = (kk * 16 + ((lane >> 3) & 1) * 8) * 2;
#pragma unroll
                for (int np = 0; np < NF2; np++) {
                    uint32_t off = swz((uint32_t)((r0 + np * 16) * 128 + c2));
                    LDSM4(bfh[np], bH + off);
                    LDSM4(bfl[np], bL + off);
                }
            }
#pragma unroll
            for (int mf = 0; mf < MF; mf++)
#pragma unroll
                for (int np = 0; np < NF2; np++) {
                    MMA16816(acc[0][mf][np * 2],     afh[mf], bfh[np][0], bfh[np][1]);
                    MMA16816(acc[0][mf][np * 2 + 1], afh[mf], bfh[np][2], bfh[np][3]);
                    MMA16816(acc[1][mf][np * 2],     afh[mf], bfl[np][0], bfl[np][1]);
                    MMA16816(acc[1][mf][np * 2 + 1], afh[mf], bfl[np][2], bfl[np][3]);
                    MMA16816(acc[2][mf][np * 2],     afl[mf], bfh[np][0], bfh[np][1]);
                    MMA16816(acc[2][mf][np * 2 + 1], afl[mf], bfh[np][2], bfh[np][3]);
                }
        }
    }

    const int g = lane >> 2, t4 = lane & 3;
#pragma unroll
    for (int mf = 0; mf < MF; mf++) {
#pragma unroll
        for (int nf = 0; nf < NF2 * 2; nf++) {
            const int n = n0 + wn * TN + (nf >> 1) * 16 + (nf & 1) * 8 + t4 * 2;
            const float b0 = bias[n], b1 = bias[n + 1];
#pragma unroll
            for (int h2 = 0; h2 < 2; h2++) {
                const size_t m = m0 + wm * TM + mf * 16 + g + h2 * 8;
                float2 o;
                o.x = acc[0][mf][nf][h2 * 2] +
                      0.03125f * (acc[1][mf][nf][h2 * 2] + acc[2][mf][nf][h2 * 2]) + b0;
                o.y = acc[0][mf][nf][h2 * 2 + 1] +
                      0.03125f * (acc[1][mf][nf][h2 * 2 + 1] + acc[2][mf][nf][h2 * 2 + 1]) + b1;
                *(float2*)(Cf + m * HID + n) = o;
            }
        }
    }
}

// ---------------- small kernels ----------------
// merged split: index i covers HID*HID; arrays 3 (fc) and 4 (emb) are smaller
__global__ __launch_bounds__(256)
void k_split_all(const float* __restrict__ whh, __half* __restrict__ whhhi,
                 __half* __restrict__ whhlos,
                 const float* __restrict__ wxh, __half* __restrict__ wxhhi,
                 __half* __restrict__ wxhlos,
                 const float* __restrict__ fcw, __half* __restrict__ fchi,
                 __half* __restrict__ fclos,
                 const float* __restrict__ emb, __half* __restrict__ embhi,
                 __half* __restrict__ emblos)
{
    int i = blockIdx.x * 256 + threadIdx.x;
    {
        float v = whh[i];
        __half h = __float2half_rn(v);
        whhhi[i]  = h;
        whhlos[i] = __float2half_rn((v - __half2float(h)) * 32.f);
    }
    {
        float v = wxh[i];
        __half h = __float2half_rn(v);
        wxhhi[i]  = h;
        wxhlos[i] = __float2half_rn((v - __half2float(h)) * 32.f);
    }
    if (i < VOCABN * HID) {
        {
            float v = fcw[i];
            __half h = __float2half_rn(v);
            fchi[i]  = h;
            fclos[i] = __float2half_rn((v - __half2float(h)) * 32.f);
        }
        {
            float v = emb[i];
            __half h = __float2half_rn(v);
            embhi[i]  = h;
            emblos[i] = __float2half_rn((v - __half2float(h)) * 32.f);
        }
    }
}

__global__ __launch_bounds__(256)
void k_step0(const int* __restrict__ x, const float* __restrict__ P,
             const float* __restrict__ bias, __half* __restrict__ hhi,
             __half* __restrict__ hlos)
{
    int idx = blockIdx.x * 256 + threadIdx.x;
    int b = idx >> 10, n = idx & (HID - 1);
    float h = tanhf(P[(size_t)x[b * SEQ] * HID + n] + bias[n]);
    __half a = __float2half_rn(h);
    hhi[idx]  = a;
    hlos[idx] = __float2half_rn((h - __half2float(a)) * 32.f);
}

__global__ void k_zero_bar() { g_bar[blockIdx.x * 256 + threadIdx.x] = 0; }

extern "C" void kernel_launch(void* const* d_in, const int* in_sizes, int n_in,
                              void* d_out, int out_size)
{
    const int*   x     = (const int*)  d_in[0];
    const float* embed = (const float*)d_in[1];
    const float* Wxh_w = (const float*)d_in[2];
    const float* Wxh_b = (const float*)d_in[3];
    const float* Whh_w = (const float*)d_in[4];
    const float* Whh_b = (const float*)d_in[5];
    const float* fc_w  = (const float*)d_in[6];
    const float* fc_b  = (const float*)d_in[7];
    float* outp = (float*)d_out;

    float* P;
    __half *hhi, *hlos, *whhhi, *whhlos, *wxhhi, *wxhlos, *embhi, *emblos, *fchi, *fclos;
    cudaGetSymbolAddress((void**)&P,      g_P);
    cudaGetSymbolAddress((void**)&hhi,    g_hhi);
    cudaGetSymbolAddress((void**)&hlos,   g_hlos);
    cudaGetSymbolAddress((void**)&whhhi,  g_whhhi);
    cudaGetSymbolAddress((void**)&whhlos, g_whhlos);
    cudaGetSymbolAddress((void**)&wxhhi,  g_wxhhi);
    cudaGetSymbolAddress((void**)&wxhlos, g_wxhlos);
    cudaGetSymbolAddress((void**)&embhi,  g_embhi);
    cudaGetSymbolAddress((void**)&emblos, g_emblos);
    cudaGetSymbolAddress((void**)&fchi,   g_fchi);
    cudaGetSymbolAddress((void**)&fclos,  g_fclos);

    const int SM_P   = (2 * 32 + 2 * 64) * 128 * 4 + 1024;    //  97 KB
    const int SM_RNN = 131072 + 3 * 32768 + 1024;             // 230400 B (225 KB)
    cudaFuncSetAttribute(k_g3<32, 64, 2, 4>,
                         cudaFuncAttributeMaxDynamicSharedMemorySize, SM_P);
    cudaFuncSetAttribute(k_fused,
                         cudaFuncAttributeMaxDynamicSharedMemorySize, SM_RNN);

    // 0) operand splits (single merged kernel)
    k_split_all<<<(HID * HID) / 256, 256>>>(Whh_w, whhhi, whhlos,
                                            Wxh_w, wxhhi, wxhlos,
                                            fc_w, fchi, fclos,
                                            embed, embhi, emblos);

    // 1) P = embed @ Wxh^T + bxh
    k_g3<32, 64, 2, 4><<<dim3(HID / 64, VOCABN / 32), 256, SM_P>>>(
        embhi, emblos, wxhhi, wxhlos, Wxh_b, P);

    // 2) t = 0
    k_step0<<<(BATCHN * HID) / 256, 256>>>(x, P, Whh_b, hhi, hlos);

    // 3) reset barriers, then fused persistent recurrence + fc consumers
    k_zero_bar<<<8, 256>>>();
    k_fused<<<NCTA + NFC, 256, SM_RNN>>>(whhhi, whhlos, Whh_b, P, x, hhi, hlos,
                                         fchi, fclos, fc_b, outp);
}